// round 1
// baseline (speedup 1.0000x reference)
#include <cuda_runtime.h>
#include <cuda_fp16.h>
#include <mma.h>
#include <math.h>

using namespace nvcuda;

// Problem constants
static constexpr int N = 512;      // batch
static constexpr int D = 512;      // features
static constexpr int C = 50000;    // classes
static constexpr float SCALE = 30.0f;
static constexpr float COS_M = 0.8775825618903728f;   // cos(0.5)
static constexpr float SIN_M = 0.479425538604203f;    // sin(0.5)
static constexpr float TH    = -0.8775825618903728f;  // cos(pi-0.5)
static constexpr float MMC   = 0.2397127693021015f;   // sin(pi-0.5)*0.5

// Device scratch (no runtime allocation allowed)
__device__ __half g_xn[(size_t)N * D];       // normalized x, fp16
__device__ __half g_wn[(size_t)C * D];       // normalized W, fp16  (51.2 MB)
__device__ float  g_rowloss[N];
__device__ float  g_out_scratch[1];          // placeholder (only used if out_size tiny; real case writes d_out)
// Full fallback scratch for the unlikely case out_size < N*C:
__device__ float  g_out_full[(size_t)N * C];

// ---------------------------------------------------------------------------
// Row L2-normalize (fp32 in -> fp16 out). One block per row, 128 threads.
// which==0 -> write g_xn, which==1 -> write g_wn
// ---------------------------------------------------------------------------
__global__ void norm_rows_kernel(const float* __restrict__ in, int which)
{
    int r = blockIdx.x;
    int t = threadIdx.x;  // 128 threads, 4 floats each (D=512)
    const float4* rp = reinterpret_cast<const float4*>(in + (size_t)r * D);
    float4 v = rp[t];
    float ss = v.x * v.x + v.y * v.y + v.z * v.z + v.w * v.w;
    #pragma unroll
    for (int o = 16; o; o >>= 1) ss += __shfl_xor_sync(0xFFFFFFFFu, ss, o);
    __shared__ float sh[4];
    if ((t & 31) == 0) sh[t >> 5] = ss;
    __syncthreads();
    float tot = sh[0] + sh[1] + sh[2] + sh[3];
    float inv = 1.0f / fmaxf(sqrtf(tot), 1e-12f);
    __half* dst = which ? g_wn : g_xn;
    __half2* op = reinterpret_cast<__half2*>(dst + (size_t)r * D);
    op[t * 2 + 0] = __floats2half2_rn(v.x * inv, v.y * inv);
    op[t * 2 + 1] = __floats2half2_rn(v.z * inv, v.w * inv);
}

// ---------------------------------------------------------------------------
// GEMM: cosine[N, C] = xn[N, D] * wn[C, D]^T  (fp16 in, fp32 acc)
// Block tile 128x128, BK=32, 8 warps (2x4), warp tile 64x32 (4x2 wmma frags).
// Fused epilogue: phi-margin at (row, label[row]) positions, scale by 30.
// ---------------------------------------------------------------------------
static constexpr int BM = 128, BN = 128, BK = 32, BKP = 40;  // BKP padded (80B rows, 16B aligned)

__global__ __launch_bounds__(256, 2)
void gemm_margin_kernel(const int* __restrict__ labels, float* __restrict__ out)
{
    // smem union: tiles (20480B) / epilogue stage (32768B)
    __shared__ __align__(16) unsigned char smraw[64 * 128 * sizeof(float)];
    __half* sA = reinterpret_cast<__half*>(smraw);
    __half* sB = reinterpret_cast<__half*>(smraw + BM * BKP * sizeof(__half));
    float*  stage = reinterpret_cast<float*>(smraw);

    const int tid  = threadIdx.x;
    const int warp = tid >> 5;
    const int wRow = warp >> 2;   // 0..1
    const int wCol = warp & 3;    // 0..3
    const int br   = blockIdx.x;  // M tile (0..3)
    const int bc   = blockIdx.y;  // C tile (0..390)

    wmma::fragment<wmma::accumulator, 16, 16, 16, float> acc[4][2];
    #pragma unroll
    for (int i = 0; i < 4; i++)
        #pragma unroll
        for (int j = 0; j < 2; j++)
            wmma::fill_fragment(acc[i][j], 0.0f);

    const int rowBase = br * BM;
    const int colBase = bc * BN;

    for (int kt = 0; kt < D / BK; kt++) {
        // Load A tile: 128 rows x 32 halves. 512 vec8 loads -> 2 per thread.
        #pragma unroll
        for (int j = 0; j < 2; j++) {
            int v   = tid + j * 256;
            int row = v >> 2;
            int cv  = v & 3;
            const uint4* gp = reinterpret_cast<const uint4*>(
                g_xn + (size_t)(rowBase + row) * D + kt * BK + cv * 8);
            *reinterpret_cast<uint4*>(sA + row * BKP + cv * 8) = *gp;
        }
        // Load B tile: 128 class rows x 32 halves, zero-fill OOB classes.
        #pragma unroll
        for (int j = 0; j < 2; j++) {
            int v   = tid + j * 256;
            int row = v >> 2;
            int cv  = v & 3;
            int cls = colBase + row;
            uint4 val = make_uint4(0, 0, 0, 0);
            if (cls < C) {
                val = *reinterpret_cast<const uint4*>(
                    g_wn + (size_t)cls * D + kt * BK + cv * 8);
            }
            *reinterpret_cast<uint4*>(sB + row * BKP + cv * 8) = val;
        }
        __syncthreads();

        #pragma unroll
        for (int ks = 0; ks < BK / 16; ks++) {
            wmma::fragment<wmma::matrix_a, 16, 16, 16, __half, wmma::row_major> af[4];
            wmma::fragment<wmma::matrix_b, 16, 16, 16, __half, wmma::col_major> bf[2];
            #pragma unroll
            for (int i = 0; i < 4; i++)
                wmma::load_matrix_sync(af[i], sA + (wRow * 64 + i * 16) * BKP + ks * 16, BKP);
            #pragma unroll
            for (int j = 0; j < 2; j++)
                wmma::load_matrix_sync(bf[j], sB + (wCol * 32 + j * 16) * BKP + ks * 16, BKP);
            #pragma unroll
            for (int i = 0; i < 4; i++)
                #pragma unroll
                for (int j = 0; j < 2; j++)
                    wmma::mma_sync(acc[i][j], af[i], bf[j], acc[i][j]);
        }
        __syncthreads();
    }

    // Epilogue in two phases (stage is 64x128 floats = 32KB, aliases tiles)
    #pragma unroll
    for (int p = 0; p < 2; p++) {
        if (wRow == p) {
            #pragma unroll
            for (int i = 0; i < 4; i++)
                #pragma unroll
                for (int j = 0; j < 2; j++)
                    wmma::store_matrix_sync(stage + (i * 16) * 128 + wCol * 32 + j * 16,
                                            acc[i][j], 128, wmma::mem_row_major);
        }
        __syncthreads();
        for (int t = tid; t < 64 * 128; t += 256) {
            int lr  = t >> 7;
            int col = t & 127;
            int gr  = rowBase + p * 64 + lr;
            int gc  = colBase + col;
            if (gc < C) {
                float c   = stage[t];
                int   lab = __ldg(labels + gr);
                float val;
                if (gc == lab) {
                    float sine = sqrtf(fmaxf(0.0f, fminf(1.0000001f - c * c, 1.0f)));
                    float ph   = c * COS_M - sine * SIN_M;
                    val = (c > TH) ? ph : (c - MMC);
                } else {
                    val = c;
                }
                out[(size_t)gr * C + gc] = val * SCALE;
            }
        }
        __syncthreads();
    }
}

// ---------------------------------------------------------------------------
// Per-row online logsumexp + CE loss. One block (256 thr) per row.
// ---------------------------------------------------------------------------
__global__ void rowloss_kernel(const float* __restrict__ out, const int* __restrict__ labels)
{
    int r   = blockIdx.x;
    int tid = threadIdx.x;
    const float4* row = reinterpret_cast<const float4*>(out + (size_t)r * C);
    float m = -1e30f, s = 0.0f;
    for (int i = tid; i < C / 4; i += 256) {
        float4 v = row[i];
        float vv[4] = { v.x, v.y, v.z, v.w };
        #pragma unroll
        for (int k = 0; k < 4; k++) {
            float x = vv[k];
            if (x <= m) {
                s += __expf(x - m);
            } else {
                s = s * __expf(m - x) + 1.0f;
                m = x;
            }
        }
    }
    // warp combine
    #pragma unroll
    for (int o = 16; o; o >>= 1) {
        float mo = __shfl_down_sync(0xFFFFFFFFu, m, o);
        float so = __shfl_down_sync(0xFFFFFFFFu, s, o);
        float M  = fmaxf(m, mo);
        s = s * __expf(m - M) + so * __expf(mo - M);
        m = M;
    }
    __shared__ float shm[8], shs[8];
    if ((tid & 31) == 0) { shm[tid >> 5] = m; shs[tid >> 5] = s; }
    __syncthreads();
    if (tid == 0) {
        float M = shm[0], S = shs[0];
        #pragma unroll
        for (int w = 1; w < 8; w++) {
            float mo = shm[w], so = shs[w];
            float Mn = fmaxf(M, mo);
            S = S * __expf(M - Mn) + so * __expf(mo - Mn);
            M = Mn;
        }
        float lse    = M + logf(S);
        int   lab    = labels[r];
        float picked = out[(size_t)r * C + lab];
        g_rowloss[r] = lse - picked;
    }
}

__global__ void finalize_kernel(float* __restrict__ dst)
{
    int tid = threadIdx.x;  // 512 threads
    float v = g_rowloss[tid];
    #pragma unroll
    for (int o = 16; o; o >>= 1) v += __shfl_xor_sync(0xFFFFFFFFu, v, o);
    __shared__ float sh[16];
    if ((tid & 31) == 0) sh[tid >> 5] = v;
    __syncthreads();
    if (tid == 0) {
        float tot = 0.0f;
        #pragma unroll
        for (int w = 0; w < 16; w++) tot += sh[w];
        dst[0] = tot / (float)N;
    }
}

// ---------------------------------------------------------------------------
extern "C" void kernel_launch(void* const* d_in, const int* in_sizes, int n_in,
                              void* d_out, int out_size)
{
    const float* logits = (const float*)d_in[0];  // [512, 512] f32
    const int*   labels = (const int*)  d_in[1];  // [512] int32
    const float* weight = (const float*)d_in[2];  // [50000, 512] f32

    const long long NC = (long long)N * C;
    float* out;
    float* lossdst = nullptr;
    if ((long long)out_size == NC + 1) {
        out = (float*)d_out;
        lossdst = (float*)d_out + NC;
    } else if ((long long)out_size == NC) {
        out = (float*)d_out;         // no room for the scalar loss
    } else {
        // output matrix doesn't fit in d_out: compute into scratch, loss -> d_out[last]
        cudaGetSymbolAddress((void**)&out, g_out_full);
        lossdst = (float*)d_out + (out_size > 0 ? out_size - 1 : 0);
    }

    // 1) normalize x and W into fp16 scratch
    norm_rows_kernel<<<N, 128>>>(logits, 0);
    norm_rows_kernel<<<C, 128>>>(weight, 1);

    // 2) GEMM + margin epilogue (grid.x = M tiles so the 4 blocks sharing a
    //    B tile are adjacent -> L2 reuse of W)
    dim3 grid(N / BM, (C + BN - 1) / BN);
    gemm_margin_kernel<<<grid, 256>>>(labels, out);

    // 3) loss
    if (lossdst) {
        rowloss_kernel<<<N, 256>>>(out, labels);
        finalize_kernel<<<1, 512>>>(lossdst);
    }
}

// round 6
// speedup vs baseline: 1.0238x; 1.0238x over previous
#include <cuda_runtime.h>
#include <cuda_fp16.h>
#include <mma.h>
#include <cstdint>
#include <math.h>

using namespace nvcuda;

// Problem constants
static constexpr int N = 512;      // batch
static constexpr int D = 512;      // features
static constexpr int C = 50000;    // classes
static constexpr float SCALE = 30.0f;
static constexpr float COS_M = 0.8775825618903728f;   // cos(0.5)
static constexpr float SIN_M = 0.479425538604203f;    // sin(0.5)
static constexpr float TH    = -0.8775825618903728f;  // cos(pi-0.5)
static constexpr float MMC   = 0.2397127693021015f;   // sin(pi-0.5)*0.5

// Device scratch (no runtime allocation allowed)
__device__ __half g_xn[(size_t)N * D];       // normalized x, fp16
__device__ __half g_wn[(size_t)C * D];       // normalized W, fp16  (51.2 MB)
__device__ float  g_rowsum[N];               // sum exp(logit - 30) per row
__device__ float  g_picked[N];               // post-margin scaled logit at label
// Fallback scratch if out_size < N*C (not expected):
__device__ float  g_out_full[(size_t)N * C];

// ---------------------------------------------------------------------------
// cp.async helpers (sm_80+, no 'a' suffix needed)
// ---------------------------------------------------------------------------
__device__ __forceinline__ uint32_t smem_u32(const void* p) {
    uint32_t a;
    asm("{ .reg .u64 t; cvta.to.shared.u64 t, %1; cvt.u32.u64 %0, t; }" : "=r"(a) : "l"(p));
    return a;
}
#define CP_ASYNC16(dst, src) \
    asm volatile("cp.async.cg.shared.global [%0], [%1], 16;" :: "r"(dst), "l"(src) : "memory")
#define CP_ASYNC16_ZF(dst, src, srcsz) \
    asm volatile("cp.async.cg.shared.global [%0], [%1], 16, %2;" :: "r"(dst), "l"(src), "r"(srcsz) : "memory")
#define CP_COMMIT() asm volatile("cp.async.commit_group;" ::: "memory")
#define CP_WAIT(n)  asm volatile("cp.async.wait_group %0;" :: "n"(n) : "memory")

// ---------------------------------------------------------------------------
// Row L2-normalize (fp32 in -> fp16 out). One block per row, 128 threads.
// ---------------------------------------------------------------------------
__global__ void norm_rows_kernel(const float* __restrict__ in, int which)
{
    int r = blockIdx.x;
    int t = threadIdx.x;  // 128 threads, 4 floats each (D=512)
    const float4* rp = reinterpret_cast<const float4*>(in + (size_t)r * D);
    float4 v = rp[t];
    float ss = v.x * v.x + v.y * v.y + v.z * v.z + v.w * v.w;
    #pragma unroll
    for (int o = 16; o; o >>= 1) ss += __shfl_xor_sync(0xFFFFFFFFu, ss, o);
    __shared__ float sh[4];
    if ((t & 31) == 0) sh[t >> 5] = ss;
    __syncthreads();
    float tot = sh[0] + sh[1] + sh[2] + sh[3];
    float inv = 1.0f / fmaxf(sqrtf(tot), 1e-12f);
    __half* dst = which ? g_wn : g_xn;
    __half2* op = reinterpret_cast<__half2*>(dst + (size_t)r * D);
    op[t * 2 + 0] = __floats2half2_rn(v.x * inv, v.y * inv);
    op[t * 2 + 1] = __floats2half2_rn(v.z * inv, v.w * inv);
}

__global__ void zero_rowsum_kernel()
{
    g_rowsum[threadIdx.x] = 0.0f;
}

// ---------------------------------------------------------------------------
// GEMM: cosine[N, C] = xn[N, D] * wn[C, D]^T  (fp16 in, fp32 acc)
// Block tile 128x128, BK=32 double-buffered via cp.async, 8 warps (2x4),
// warp tile 64x32 (4x2 wmma frags).
// Fused epilogue: phi-margin at label col, x30 scale, per-row exp-sum
// (fixed max 30) -> g_rowsum, coalesced stores.
// ---------------------------------------------------------------------------
static constexpr int BM = 128, BN = 128, BK = 32, BKP = 40;  // BKP padded (80B rows)
static constexpr int STAGE_BYTES = 2 * (BM * BKP) * (int)sizeof(__half);  // A+B = 20480
static constexpr int KITERS = D / BK;                                      // 16
static constexpr int ROWSUM_OFF = 2 * STAGE_BYTES;                         // 40960
static constexpr int SMEM_TOTAL = ROWSUM_OFF + 128 * (int)sizeof(float);   // 41472

__global__ void __launch_bounds__(256, 2)
gemm_margin_kernel(const int* __restrict__ labels, float* __restrict__ out)
{
    extern __shared__ __align__(16) unsigned char smraw[];
    const uint32_t smb = smem_u32(smraw);
    float* shRow = reinterpret_cast<float*>(smraw + ROWSUM_OFF);
    float* stage = reinterpret_cast<float*>(smraw);    // epilogue union (32KB)

    const int tid  = threadIdx.x;
    const int warp = tid >> 5;
    const int lane = tid & 31;
    const int wRow = warp >> 2;   // 0..1
    const int wCol = warp & 3;    // 0..3
    const int rowBase = blockIdx.x * BM;
    const int colBase = blockIdx.y * BN;

    if (tid < 128) shRow[tid] = 0.0f;

    wmma::fragment<wmma::accumulator, 16, 16, 16, float> acc[4][2];
    #pragma unroll
    for (int i = 0; i < 4; i++)
        #pragma unroll
        for (int j = 0; j < 2; j++)
            wmma::fill_fragment(acc[i][j], 0.0f);

    // Per-thread load coordinates (2 uint4 per tile per thread)
    // v = tid + j*256 ; row = v>>2 ; chunk = v&3 (8 halves each)
    auto prefetch = [&](int kt) {
        const int slot = kt & 1;
        const uint32_t sA = smb + slot * STAGE_BYTES;
        const uint32_t sB = sA + BM * BKP * (int)sizeof(__half);
        #pragma unroll
        for (int j = 0; j < 2; j++) {
            int v   = tid + j * 256;
            int row = v >> 2;
            int cv  = v & 3;
            const __half* asrc = g_xn + (size_t)(rowBase + row) * D + kt * BK + cv * 8;
            CP_ASYNC16(sA + (uint32_t)(row * BKP + cv * 8) * 2, asrc);
        }
        #pragma unroll
        for (int j = 0; j < 2; j++) {
            int v   = tid + j * 256;
            int row = v >> 2;
            int cv  = v & 3;
            int cls = colBase + row;
            const __half* bsrc = g_wn + (size_t)cls * D + kt * BK + cv * 8;
            uint32_t sz = (cls < C) ? 16u : 0u;   // zero-fill OOB class rows
            CP_ASYNC16_ZF(sB + (uint32_t)(row * BKP + cv * 8) * 2, bsrc, sz);
        }
        CP_COMMIT();
    };

    prefetch(0);
    prefetch(1);

    for (int kt = 0; kt < KITERS; kt++) {
        if (kt == KITERS - 1) { CP_WAIT(0); } else { CP_WAIT(1); }
        __syncthreads();

        const int slot = kt & 1;
        const __half* sA = reinterpret_cast<const __half*>(smraw + slot * STAGE_BYTES);
        const __half* sB = sA + BM * BKP;

        #pragma unroll
        for (int ks = 0; ks < BK / 16; ks++) {
            wmma::fragment<wmma::matrix_a, 16, 16, 16, __half, wmma::row_major> af[4];
            wmma::fragment<wmma::matrix_b, 16, 16, 16, __half, wmma::col_major> bf[2];
            #pragma unroll
            for (int i = 0; i < 4; i++)
                wmma::load_matrix_sync(af[i], sA + (wRow * 64 + i * 16) * BKP + ks * 16, BKP);
            #pragma unroll
            for (int j = 0; j < 2; j++)
                wmma::load_matrix_sync(bf[j], sB + (wCol * 32 + j * 16) * BKP + ks * 16, BKP);
            #pragma unroll
            for (int i = 0; i < 4; i++)
                #pragma unroll
                for (int j = 0; j < 2; j++)
                    wmma::mma_sync(acc[i][j], af[i], bf[j], acc[i][j]);
        }
        __syncthreads();   // everyone done with this slot before refill
        if (kt + 2 < KITERS) prefetch(kt + 2);
    }

    // ------------------ fused epilogue -----------------------------------
    // Two phases of 64 rows; stage is 64x128 floats (aliases the tiles).
    #pragma unroll
    for (int p = 0; p < 2; p++) {
        if (wRow == p) {
            #pragma unroll
            for (int i = 0; i < 4; i++)
                #pragma unroll
                for (int j = 0; j < 2; j++)
                    wmma::store_matrix_sync(stage + (i * 16) * 128 + wCol * 32 + j * 16,
                                            acc[i][j], 128, wmma::mem_row_major);
        }
        __syncthreads();
        // Copy loop: warp-uniform row per iteration -> warp-reduce expsum.
        #pragma unroll 4
        for (int k = 0; k < 32; k++) {
            int t   = tid + k * 256;
            int lr  = t >> 7;          // 0..63, warp-uniform
            int col = t & 127;
            int gr  = rowBase + p * 64 + lr;
            int gc  = colBase + col;
            float e = 0.0f;
            if (gc < C) {
                float c   = stage[t];
                int   lab = __ldg(labels + gr);
                float val;
                if (gc == lab) {
                    float sine = sqrtf(fmaxf(0.0f, fminf(1.0000001f - c * c, 1.0f)));
                    float ph   = c * COS_M - sine * SIN_M;
                    val = ((c > TH) ? ph : (c - MMC)) * SCALE;
                    g_picked[gr] = val;
                } else {
                    val = c * SCALE;
                }
                out[(size_t)gr * C + gc] = val;
                e = __expf(val - 30.0f);
            }
            #pragma unroll
            for (int o = 16; o; o >>= 1) e += __shfl_xor_sync(0xFFFFFFFFu, e, o);
            if (lane == 0) atomicAdd(&shRow[p * 64 + lr], e);
        }
        __syncthreads();
    }
    if (tid < 128) atomicAdd(&g_rowsum[rowBase + tid], shRow[tid]);
}

// ---------------------------------------------------------------------------
// Final loss: lse_r = 30 + log(rowsum_r); loss = mean(lse - picked)
// ---------------------------------------------------------------------------
__global__ void finalize_kernel(float* __restrict__ dst)
{
    int tid = threadIdx.x;   // 512 threads
    float v = (30.0f + logf(g_rowsum[tid])) - g_picked[tid];
    #pragma unroll
    for (int o = 16; o; o >>= 1) v += __shfl_xor_sync(0xFFFFFFFFu, v, o);
    __shared__ float sh[16];
    if ((tid & 31) == 0) sh[tid >> 5] = v;
    __syncthreads();
    if (tid == 0) {
        float tot = 0.0f;
        #pragma unroll
        for (int w = 0; w < 16; w++) tot += sh[w];
        dst[0] = tot / (float)N;
    }
}

// ---------------------------------------------------------------------------
extern "C" void kernel_launch(void* const* d_in, const int* in_sizes, int n_in,
                              void* d_out, int out_size)
{
    const float* logits = (const float*)d_in[0];  // [512, 512] f32
    const int*   labels = (const int*)  d_in[1];  // [512] int32
    const float* weight = (const float*)d_in[2];  // [50000, 512] f32

    const long long NC = (long long)N * C;
    float* out;
    float* lossdst = nullptr;
    if ((long long)out_size == NC + 1) {
        out = (float*)d_out;
        lossdst = (float*)d_out + NC;
    } else if ((long long)out_size == NC) {
        out = (float*)d_out;
    } else {
        cudaGetSymbolAddress((void**)&out, g_out_full);
        lossdst = (float*)d_out + (out_size > 0 ? out_size - 1 : 0);
    }

    cudaFuncSetAttribute(gemm_margin_kernel, cudaFuncAttributeMaxDynamicSharedMemorySize, SMEM_TOTAL);

    zero_rowsum_kernel<<<1, N>>>();
    norm_rows_kernel<<<N, 128>>>(logits, 0);
    norm_rows_kernel<<<C, 128>>>(weight, 1);

    // grid.x = M tiles fastest -> 4 blocks sharing a W tile run adjacently (L2 reuse)
    dim3 grid(N / BM, (C + BN - 1) / BN);
    gemm_margin_kernel<<<grid, 256, SMEM_TOTAL>>>(labels, out);

    if (lossdst) {
        finalize_kernel<<<1, N>>>(lossdst);
    }
}

// round 7
// speedup vs baseline: 1.5337x; 1.4981x over previous
#include <cuda_runtime.h>
#include <cuda_fp16.h>
#include <mma.h>
#include <cstdint>
#include <math.h>

using namespace nvcuda;

// Problem constants
static constexpr int N = 512;      // batch
static constexpr int D = 512;      // features
static constexpr int C = 50000;    // classes
static constexpr float SCALE = 30.0f;
static constexpr float COS_M = 0.8775825618903728f;   // cos(0.5)
static constexpr float SIN_M = 0.479425538604203f;    // sin(0.5)
static constexpr float TH    = -0.8775825618903728f;  // cos(pi-0.5)
static constexpr float MMC   = 0.2397127693021015f;   // sin(pi-0.5)*0.5

// Device scratch (no runtime allocation allowed)
__device__ __half g_xn[(size_t)N * D];       // normalized x, fp16
__device__ __half g_wn[(size_t)C * D];       // normalized W, fp16  (51.2 MB)
__device__ float  g_rowsum[N];               // sum exp(logit - 30) per row
__device__ float  g_picked[N];               // post-margin scaled logit at label
// Fallback scratch if out_size < N*C (not expected):
__device__ float  g_out_full[(size_t)N * C];

// ---------------------------------------------------------------------------
__device__ __forceinline__ uint32_t smem_u32(const void* p) {
    uint32_t a;
    asm("{ .reg .u64 t; cvta.to.shared.u64 t, %1; cvt.u32.u64 %0, t; }" : "=r"(a) : "l"(p));
    return a;
}
#define CP_ASYNC16(dst, src) \
    asm volatile("cp.async.cg.shared.global [%0], [%1], 16;" :: "r"(dst), "l"(src) : "memory")
#define CP_ASYNC16_ZF(dst, src, srcsz) \
    asm volatile("cp.async.cg.shared.global [%0], [%1], 16, %2;" :: "r"(dst), "l"(src), "r"(srcsz) : "memory")
#define CP_COMMIT() asm volatile("cp.async.commit_group;" ::: "memory")
#define CP_WAIT(n)  asm volatile("cp.async.wait_group %0;" :: "n"(n) : "memory")

// ---------------------------------------------------------------------------
// Row L2-normalize (fp32 in -> fp16 out). Warp per row, 8 rows per block.
// ---------------------------------------------------------------------------
__global__ void norm_rows_kernel(const float* __restrict__ in, int which)
{
    const int warp = threadIdx.x >> 5;
    const int lane = threadIdx.x & 31;
    const int r = blockIdx.x * 8 + warp;
    const float4* rp = reinterpret_cast<const float4*>(in + (size_t)r * D);
    float4 v[4];
    float ss = 0.0f;
    #pragma unroll
    for (int i = 0; i < 4; i++) {
        v[i] = rp[lane + 32 * i];
        ss += v[i].x * v[i].x + v[i].y * v[i].y + v[i].z * v[i].z + v[i].w * v[i].w;
    }
    #pragma unroll
    for (int o = 16; o; o >>= 1) ss += __shfl_xor_sync(0xFFFFFFFFu, ss, o);
    float inv = 1.0f / fmaxf(sqrtf(ss), 1e-12f);
    __half* dst = which ? g_wn : g_xn;
    __half2* op = reinterpret_cast<__half2*>(dst + (size_t)r * D);
    #pragma unroll
    for (int i = 0; i < 4; i++) {
        op[(lane + 32 * i) * 2 + 0] = __floats2half2_rn(v[i].x * inv, v[i].y * inv);
        op[(lane + 32 * i) * 2 + 1] = __floats2half2_rn(v[i].z * inv, v[i].w * inv);
    }
}

__global__ void zero_rowsum_kernel()
{
    g_rowsum[threadIdx.x] = 0.0f;
}

// ---------------------------------------------------------------------------
// GEMM: cosine[N, C] = xn[N, D] * wn[C, D]^T  (fp16 in, fp32 acc)
// Block tile 128x128, BK=32, 4-stage cp.async pipeline, ONE sync per K-iter.
// 8 warps (2x4), warp tile 64x32 (4x2 wmma frags).
// Fused epilogue: phi-margin at label col, x30 scale, per-row exp-sum
// (fixed max 30) -> g_rowsum, warp-per-row float4 stores.
// ---------------------------------------------------------------------------
static constexpr int BM = 128, BN = 128, BK = 32, BKP = 40;  // BKP padded (80B rows)
static constexpr int STAGE_BYTES = 2 * (BM * BKP) * (int)sizeof(__half);  // A+B = 20480
static constexpr int NSTAGE = 4;
static constexpr int KITERS = D / BK;                                      // 16
static constexpr int PIPE_BYTES = NSTAGE * STAGE_BYTES;                    // 81920
static constexpr int ROWSUM_OFF = PIPE_BYTES;                              // 81920
static constexpr int LAB_OFF    = ROWSUM_OFF + 128 * (int)sizeof(float);   // 82432
static constexpr int SMEM_TOTAL = LAB_OFF + 128 * (int)sizeof(int);        // 82944

__global__ void __launch_bounds__(256, 2)
gemm_margin_kernel(const int* __restrict__ labels, float* __restrict__ out)
{
    extern __shared__ __align__(16) unsigned char smraw[];
    const uint32_t smb = smem_u32(smraw);
    float* shRow = reinterpret_cast<float*>(smraw + ROWSUM_OFF);
    int*   shLab = reinterpret_cast<int*>(smraw + LAB_OFF);
    float* stage = reinterpret_cast<float*>(smraw);    // epilogue union (64KB of pipe)

    const int tid  = threadIdx.x;
    const int warp = tid >> 5;
    const int lane = tid & 31;
    const int wRow = warp >> 2;   // 0..1
    const int wCol = warp & 3;    // 0..3
    const int rowBase = blockIdx.x * BM;
    const int colBase = blockIdx.y * BN;

    if (tid < 128) {
        shRow[tid] = 0.0f;
        shLab[tid] = labels[rowBase + tid];
    }

    wmma::fragment<wmma::accumulator, 16, 16, 16, float> acc[4][2];
    #pragma unroll
    for (int i = 0; i < 4; i++)
        #pragma unroll
        for (int j = 0; j < 2; j++)
            wmma::fill_fragment(acc[i][j], 0.0f);

    // Per-thread load coordinates (2 uint4 per operand tile per thread)
    auto prefetch = [&](int kt) {
        const int slot = kt & (NSTAGE - 1);
        const uint32_t sA = smb + slot * STAGE_BYTES;
        const uint32_t sB = sA + BM * BKP * (int)sizeof(__half);
        #pragma unroll
        for (int j = 0; j < 2; j++) {
            int v   = tid + j * 256;
            int row = v >> 2;
            int cv  = v & 3;
            const __half* asrc = g_xn + (size_t)(rowBase + row) * D + kt * BK + cv * 8;
            CP_ASYNC16(sA + (uint32_t)(row * BKP + cv * 8) * 2, asrc);
        }
        #pragma unroll
        for (int j = 0; j < 2; j++) {
            int v   = tid + j * 256;
            int row = v >> 2;
            int cv  = v & 3;
            int cls = colBase + row;
            const __half* bsrc = g_wn + (size_t)cls * D + kt * BK + cv * 8;
            uint32_t sz = (cls < C) ? 16u : 0u;   // zero-fill OOB class rows
            CP_ASYNC16_ZF(sB + (uint32_t)(row * BKP + cv * 8) * 2, bsrc, sz);
        }
        CP_COMMIT();
    };

    prefetch(0);
    prefetch(1);
    prefetch(2);

    for (int kt = 0; kt < KITERS; kt++) {
        if (kt < KITERS - 2) { CP_WAIT(2); } else { CP_WAIT(0); }
        __syncthreads();                          // all warps done with kt-1

        if (kt + 3 < KITERS) prefetch(kt + 3);    // refill slot (kt-1)&3

        const int slot = kt & (NSTAGE - 1);
        const __half* sA = reinterpret_cast<const __half*>(smraw + slot * STAGE_BYTES);
        const __half* sB = sA + BM * BKP;

        #pragma unroll
        for (int ks = 0; ks < BK / 16; ks++) {
            wmma::fragment<wmma::matrix_a, 16, 16, 16, __half, wmma::row_major> af[4];
            wmma::fragment<wmma::matrix_b, 16, 16, 16, __half, wmma::col_major> bf[2];
            #pragma unroll
            for (int i = 0; i < 4; i++)
                wmma::load_matrix_sync(af[i], sA + (wRow * 64 + i * 16) * BKP + ks * 16, BKP);
            #pragma unroll
            for (int j = 0; j < 2; j++)
                wmma::load_matrix_sync(bf[j], sB + (wCol * 32 + j * 16) * BKP + ks * 16, BKP);
            #pragma unroll
            for (int i = 0; i < 4; i++)
                #pragma unroll
                for (int j = 0; j < 2; j++)
                    wmma::mma_sync(acc[i][j], af[i], bf[j], acc[i][j]);
        }
    }

    // ------------------ fused epilogue -----------------------------------
    __syncthreads();   // mainloop smem reads done; safe to overwrite with stage
    #pragma unroll
    for (int i = 0; i < 4; i++)
        #pragma unroll
        for (int j = 0; j < 2; j++)
            wmma::store_matrix_sync(stage + (wRow * 64 + i * 16) * 128 + wCol * 32 + j * 16,
                                    acc[i][j], 128, wmma::mem_row_major);
    __syncthreads();

    // Warp-per-row processing: 8 warps x 16 iters cover 128 rows.
    #pragma unroll 2
    for (int k = 0; k < 16; k++) {
        const int row = warp + k * 8;             // 0..127, warp-uniform
        const int gr  = rowBase + row;
        const int lab = shLab[row];
        const int gc0 = colBase + lane * 4;
        const float* sp = stage + row * 128 + lane * 4;
        float4 v = make_float4(sp[0], sp[1], sp[2], sp[3]);
        float e = 0.0f;
        float* vv = &v.x;
        #pragma unroll
        for (int j = 0; j < 4; j++) {
            float cv = vv[j];
            float val;
            if (gc0 + j == lab) {
                float sine = sqrtf(fmaxf(0.0f, fminf(1.0000001f - cv * cv, 1.0f)));
                float ph   = cv * COS_M - sine * SIN_M;
                val = ((cv > TH) ? ph : (cv - MMC)) * SCALE;
                g_picked[gr] = val;
            } else {
                val = cv * SCALE;
            }
            vv[j] = val;
            e += __expf(val - 30.0f);
        }
        if (gc0 < C) {
            *reinterpret_cast<float4*>(out + (size_t)gr * C + gc0) = v;
        } else {
            e = 0.0f;
        }
        #pragma unroll
        for (int o = 16; o; o >>= 1) e += __shfl_xor_sync(0xFFFFFFFFu, e, o);
        if (lane == 0) atomicAdd(&shRow[row], e);
    }
    __syncthreads();
    if (tid < 128) atomicAdd(&g_rowsum[rowBase + tid], shRow[tid]);
}

// ---------------------------------------------------------------------------
// Final loss: lse_r = 30 + log(rowsum_r); loss = mean(lse - picked)
// ---------------------------------------------------------------------------
__global__ void finalize_kernel(float* __restrict__ dst)
{
    int tid = threadIdx.x;   // 512 threads
    float v = (30.0f + logf(g_rowsum[tid])) - g_picked[tid];
    #pragma unroll
    for (int o = 16; o; o >>= 1) v += __shfl_xor_sync(0xFFFFFFFFu, v, o);
    __shared__ float sh[16];
    if ((tid & 31) == 0) sh[tid >> 5] = v;
    __syncthreads();
    if (tid == 0) {
        float tot = 0.0f;
        #pragma unroll
        for (int w = 0; w < 16; w++) tot += sh[w];
        dst[0] = tot / (float)N;
    }
}

// ---------------------------------------------------------------------------
extern "C" void kernel_launch(void* const* d_in, const int* in_sizes, int n_in,
                              void* d_out, int out_size)
{
    const float* logits = (const float*)d_in[0];  // [512, 512] f32
    const int*   labels = (const int*)  d_in[1];  // [512] int32
    const float* weight = (const float*)d_in[2];  // [50000, 512] f32

    const long long NC = (long long)N * C;
    float* out;
    float* lossdst = nullptr;
    if ((long long)out_size == NC + 1) {
        out = (float*)d_out;
        lossdst = (float*)d_out + NC;
    } else if ((long long)out_size == NC) {
        out = (float*)d_out;
    } else {
        cudaGetSymbolAddress((void**)&out, g_out_full);
        lossdst = (float*)d_out + (out_size > 0 ? out_size - 1 : 0);
    }

    cudaFuncSetAttribute(gemm_margin_kernel, cudaFuncAttributeMaxDynamicSharedMemorySize, SMEM_TOTAL);

    zero_rowsum_kernel<<<1, N>>>();
    norm_rows_kernel<<<N / 8, 256>>>(logits, 0);
    norm_rows_kernel<<<C / 8, 256>>>(weight, 1);

    // grid.x = M tiles fastest -> 4 blocks sharing a W tile run adjacently (L2 reuse)
    dim3 grid(N / BM, (C + BN - 1) / BN);
    gemm_margin_kernel<<<grid, 256, SMEM_TOTAL>>>(labels, out);

    if (lossdst) {
        finalize_kernel<<<1, N>>>(lossdst);
    }
}

// round 8
// speedup vs baseline: 1.6166x; 1.0540x over previous
#include <cuda_runtime.h>
#include <cuda_fp16.h>
#include <mma.h>
#include <cstdint>
#include <math.h>

using namespace nvcuda;

// Problem constants
static constexpr int N = 512;      // batch
static constexpr int D = 512;      // features
static constexpr int C = 50000;    // classes
static constexpr float SCALE = 30.0f;
static constexpr float COS_M = 0.8775825618903728f;   // cos(0.5)
static constexpr float SIN_M = 0.479425538604203f;    // sin(0.5)
static constexpr float TH    = -0.8775825618903728f;  // cos(pi-0.5)
static constexpr float MMC   = 0.2397127693021015f;   // sin(pi-0.5)*0.5

// Device scratch (no runtime allocation allowed)
__device__ __half g_xn[(size_t)N * D];       // normalized x, fp16
__device__ __half g_wn[(size_t)C * D];       // normalized W, fp16  (51.2 MB)
__device__ float  g_rowsum[N];               // sum exp(logit - 30) per row
__device__ float  g_picked[N];               // post-margin scaled logit at label
// Fallback scratch if out_size < N*C (not expected):
__device__ float  g_out_full[(size_t)N * C];

// ---------------------------------------------------------------------------
__device__ __forceinline__ uint32_t smem_u32(const void* p) {
    uint32_t a;
    asm("{ .reg .u64 t; cvta.to.shared.u64 t, %1; cvt.u32.u64 %0, t; }" : "=r"(a) : "l"(p));
    return a;
}
#define CP_ASYNC16(dst, src) \
    asm volatile("cp.async.cg.shared.global [%0], [%1], 16;" :: "r"(dst), "l"(src) : "memory")
#define CP_ASYNC16_ZF(dst, src, srcsz) \
    asm volatile("cp.async.cg.shared.global [%0], [%1], 16, %2;" :: "r"(dst), "l"(src), "r"(srcsz) : "memory")
#define CP_COMMIT() asm volatile("cp.async.commit_group;" ::: "memory")
#define CP_WAIT(n)  asm volatile("cp.async.wait_group %0;" :: "n"(n) : "memory")

// ---------------------------------------------------------------------------
// Row L2-normalize (fp32 in -> fp16 out). Warp per row, 8 rows per block.
// ---------------------------------------------------------------------------
__global__ void norm_rows_kernel(const float* __restrict__ in, int which)
{
    const int warp = threadIdx.x >> 5;
    const int lane = threadIdx.x & 31;
    const int r = blockIdx.x * 8 + warp;
    const float4* rp = reinterpret_cast<const float4*>(in + (size_t)r * D);
    float4 v[4];
    float ss = 0.0f;
    #pragma unroll
    for (int i = 0; i < 4; i++) {
        v[i] = rp[lane + 32 * i];
        ss += v[i].x * v[i].x + v[i].y * v[i].y + v[i].z * v[i].z + v[i].w * v[i].w;
    }
    #pragma unroll
    for (int o = 16; o; o >>= 1) ss += __shfl_xor_sync(0xFFFFFFFFu, ss, o);
    float inv = 1.0f / fmaxf(sqrtf(ss), 1e-12f);
    __half* dst = which ? g_wn : g_xn;
    __half2* op = reinterpret_cast<__half2*>(dst + (size_t)r * D);
    #pragma unroll
    for (int i = 0; i < 4; i++) {
        op[(lane + 32 * i) * 2 + 0] = __floats2half2_rn(v[i].x * inv, v[i].y * inv);
        op[(lane + 32 * i) * 2 + 1] = __floats2half2_rn(v[i].z * inv, v[i].w * inv);
    }
}

__global__ void zero_rowsum_kernel()
{
    g_rowsum[threadIdx.x] = 0.0f;
}

// ---------------------------------------------------------------------------
// GEMM: cosine[N, C] = xn[N, D] * wn[C, D]^T  (fp16 in, fp32 acc)
// Block tile 128x128, BK=64, 3-stage cp.async pipeline, ONE sync per K-iter
// (8 iters total). 8 warps (2x4), warp tile 64x32 (4x2 wmma frags).
// Fused epilogue: phi-margin at label col, x30 scale, per-row exp-sum
// (fixed max 30) -> g_rowsum, warp-per-row float4 stores.
// ---------------------------------------------------------------------------
static constexpr int BM = 128, BN = 128, BK = 64, BKP = 72;  // BKP: 144B rows, conflict-free
static constexpr int STAGE_BYTES = 2 * (BM * BKP) * (int)sizeof(__half);   // A+B = 36864
static constexpr int NSTAGE = 3;
static constexpr int KITERS = D / BK;                                      // 8
static constexpr int PIPE_BYTES = NSTAGE * STAGE_BYTES;                    // 110592
static constexpr int ROWSUM_OFF = PIPE_BYTES;
static constexpr int LAB_OFF    = ROWSUM_OFF + 128 * (int)sizeof(float);
static constexpr int SMEM_TOTAL = LAB_OFF + 128 * (int)sizeof(int);        // 111616

__global__ void __launch_bounds__(256, 2)
gemm_margin_kernel(const int* __restrict__ labels, float* __restrict__ out)
{
    extern __shared__ __align__(16) unsigned char smraw[];
    const uint32_t smb = smem_u32(smraw);
    float* shRow = reinterpret_cast<float*>(smraw + ROWSUM_OFF);
    int*   shLab = reinterpret_cast<int*>(smraw + LAB_OFF);
    float* stage = reinterpret_cast<float*>(smraw);    // epilogue union (64KB of pipe)

    const int tid  = threadIdx.x;
    const int warp = tid >> 5;
    const int lane = tid & 31;
    const int wRow = warp >> 2;   // 0..1
    const int wCol = warp & 3;    // 0..3
    const int rowBase = blockIdx.x * BM;
    const int colBase = blockIdx.y * BN;

    if (tid < 128) {
        shRow[tid] = 0.0f;
        shLab[tid] = labels[rowBase + tid];
    }

    wmma::fragment<wmma::accumulator, 16, 16, 16, float> acc[4][2];
    #pragma unroll
    for (int i = 0; i < 4; i++)
        #pragma unroll
        for (int j = 0; j < 2; j++)
            wmma::fill_fragment(acc[i][j], 0.0f);

    // Per-stage loads: 128 rows x 8 chunks(16B) per operand = 1024 vec / 256 thr
    // = 4 per thread per operand.
    auto prefetch = [&](int kt) {
        const int slot = kt % NSTAGE;
        const uint32_t sA = smb + slot * STAGE_BYTES;
        const uint32_t sB = sA + BM * BKP * (int)sizeof(__half);
        #pragma unroll
        for (int j = 0; j < 4; j++) {
            int v   = tid + j * 256;
            int row = v >> 3;
            int cv  = v & 7;
            const __half* asrc = g_xn + (size_t)(rowBase + row) * D + kt * BK + cv * 8;
            CP_ASYNC16(sA + (uint32_t)(row * BKP + cv * 8) * 2, asrc);
        }
        #pragma unroll
        for (int j = 0; j < 4; j++) {
            int v   = tid + j * 256;
            int row = v >> 3;
            int cv  = v & 7;
            int cls = colBase + row;
            const __half* bsrc = g_wn + (size_t)cls * D + kt * BK + cv * 8;
            uint32_t sz = (cls < C) ? 16u : 0u;   // zero-fill OOB class rows
            CP_ASYNC16_ZF(sB + (uint32_t)(row * BKP + cv * 8) * 2, bsrc, sz);
        }
        CP_COMMIT();
    };

    prefetch(0);
    prefetch(1);

    for (int kt = 0; kt < KITERS; kt++) {
        if (kt < KITERS - 1) { CP_WAIT(1); } else { CP_WAIT(0); }
        __syncthreads();                          // all warps done with slot being refilled

        if (kt + 2 < KITERS) prefetch(kt + 2);    // refill slot (kt-1)%3

        const int slot = kt % NSTAGE;
        const __half* sA = reinterpret_cast<const __half*>(smraw + slot * STAGE_BYTES);
        const __half* sB = sA + BM * BKP;

        #pragma unroll
        for (int ks = 0; ks < BK / 16; ks++) {
            wmma::fragment<wmma::matrix_a, 16, 16, 16, __half, wmma::row_major> af[4];
            wmma::fragment<wmma::matrix_b, 16, 16, 16, __half, wmma::col_major> bf[2];
            #pragma unroll
            for (int i = 0; i < 4; i++)
                wmma::load_matrix_sync(af[i], sA + (wRow * 64 + i * 16) * BKP + ks * 16, BKP);
            #pragma unroll
            for (int j = 0; j < 2; j++)
                wmma::load_matrix_sync(bf[j], sB + (wCol * 32 + j * 16) * BKP + ks * 16, BKP);
            #pragma unroll
            for (int i = 0; i < 4; i++)
                #pragma unroll
                for (int j = 0; j < 2; j++)
                    wmma::mma_sync(acc[i][j], af[i], bf[j], acc[i][j]);
        }
    }

    // ------------------ fused epilogue -----------------------------------
    __syncthreads();   // mainloop smem reads done; safe to overwrite with stage
    #pragma unroll
    for (int i = 0; i < 4; i++)
        #pragma unroll
        for (int j = 0; j < 2; j++)
            wmma::store_matrix_sync(stage + (wRow * 64 + i * 16) * 128 + wCol * 32 + j * 16,
                                    acc[i][j], 128, wmma::mem_row_major);
    __syncthreads();

    // Warp-per-row processing: 8 warps x 16 iters cover 128 rows.
    #pragma unroll 2
    for (int k = 0; k < 16; k++) {
        const int row = warp + k * 8;             // 0..127, warp-uniform
        const int gr  = rowBase + row;
        const int lab = shLab[row];
        const int gc0 = colBase + lane * 4;
        const float* sp = stage + row * 128 + lane * 4;
        float4 v = make_float4(sp[0], sp[1], sp[2], sp[3]);
        float e = 0.0f;
        float* vv = &v.x;
        #pragma unroll
        for (int j = 0; j < 4; j++) {
            float cv = vv[j];
            float val;
            if (gc0 + j == lab) {
                float sine = sqrtf(fmaxf(0.0f, fminf(1.0000001f - cv * cv, 1.0f)));
                float ph   = cv * COS_M - sine * SIN_M;
                val = ((cv > TH) ? ph : (cv - MMC)) * SCALE;
                g_picked[gr] = val;
            } else {
                val = cv * SCALE;
            }
            vv[j] = val;
            e += __expf(val - 30.0f);
        }
        if (gc0 < C) {
            *reinterpret_cast<float4*>(out + (size_t)gr * C + gc0) = v;
        } else {
            e = 0.0f;
        }
        #pragma unroll
        for (int o = 16; o; o >>= 1) e += __shfl_xor_sync(0xFFFFFFFFu, e, o);
        if (lane == 0) atomicAdd(&shRow[row], e);
    }
    __syncthreads();
    if (tid < 128) atomicAdd(&g_rowsum[rowBase + tid], shRow[tid]);
}

// ---------------------------------------------------------------------------
// Final loss: lse_r = 30 + log(rowsum_r); loss = mean(lse - picked)
// ---------------------------------------------------------------------------
__global__ void finalize_kernel(float* __restrict__ dst)
{
    int tid = threadIdx.x;   // 512 threads
    float v = (30.0f + logf(g_rowsum[tid])) - g_picked[tid];
    #pragma unroll
    for (int o = 16; o; o >>= 1) v += __shfl_xor_sync(0xFFFFFFFFu, v, o);
    __shared__ float sh[16];
    if ((tid & 31) == 0) sh[tid >> 5] = v;
    __syncthreads();
    if (tid == 0) {
        float tot = 0.0f;
        #pragma unroll
        for (int w = 0; w < 16; w++) tot += sh[w];
        dst[0] = tot / (float)N;
    }
}

// ---------------------------------------------------------------------------
extern "C" void kernel_launch(void* const* d_in, const int* in_sizes, int n_in,
                              void* d_out, int out_size)
{
    const float* logits = (const float*)d_in[0];  // [512, 512] f32
    const int*   labels = (const int*)  d_in[1];  // [512] int32
    const float* weight = (const float*)d_in[2];  // [50000, 512] f32

    const long long NC = (long long)N * C;
    float* out;
    float* lossdst = nullptr;
    if ((long long)out_size == NC + 1) {
        out = (float*)d_out;
        lossdst = (float*)d_out + NC;
    } else if ((long long)out_size == NC) {
        out = (float*)d_out;
    } else {
        cudaGetSymbolAddress((void**)&out, g_out_full);
        lossdst = (float*)d_out + (out_size > 0 ? out_size - 1 : 0);
    }

    cudaFuncSetAttribute(gemm_margin_kernel, cudaFuncAttributeMaxDynamicSharedMemorySize, SMEM_TOTAL);

    zero_rowsum_kernel<<<1, N>>>();
    norm_rows_kernel<<<N / 8, 256>>>(logits, 0);
    norm_rows_kernel<<<C / 8, 256>>>(weight, 1);

    // grid.x = M tiles fastest -> 4 blocks sharing a W tile run adjacently (L2 reuse)
    dim3 grid(N / BM, (C + BN - 1) / BN);
    gemm_margin_kernel<<<grid, 256, SMEM_TOTAL>>>(labels, out);

    if (lossdst) {
        finalize_kernel<<<1, N>>>(lossdst);
    }
}